// round 1
// baseline (speedup 1.0000x reference)
#include <cuda_runtime.h>
#include <math.h>
#include <stdint.h>

#define Nn      8192
#define NFEATC  512
#define NHID    256
#define NCLASS  16
#define MAXDEG  160
#define ALPHAC  0.01f
#define CATW    (NHID + NCLASS)   /* 272 */

/* ---------------- device scratch (no allocs allowed) ---------------- */
__device__ int   g_col[Nn * MAXDEG];
__device__ int   g_cnt[Nn];
__device__ float g_XW[Nn * NHID];
__device__ float g_h1[Nn * NHID];
__device__ float g_Wh[Nn * NHID];
__device__ float g_f1[Nn];
__device__ float g_f2[Nn];
__device__ float g_aW3[Nn * NCLASS];

/* ---------------- K1: deterministic ordered CSR build ---------------- */
__global__ __launch_bounds__(256) void build_csr(const int* __restrict__ adj) {
    int row  = blockIdx.x;
    int tid  = threadIdx.x;
    int lane = tid & 31, wid = tid >> 5;
    __shared__ int s_w[8];
    __shared__ int s_base;
    if (tid == 0) s_base = 0;
    __syncthreads();
    const int* arow = adj + (size_t)row * Nn;
    for (int c0 = 0; c0 < Nn; c0 += 256) {
        int v = arow[c0 + tid];
        unsigned b = __ballot_sync(0xffffffffu, v != 0);
        if (lane == 0) s_w[wid] = __popc(b);
        __syncthreads();
        if (tid == 0) {
            int s = s_base;
#pragma unroll
            for (int w = 0; w < 8; w++) { int t = s_w[w]; s_w[w] = s; s += t; }
            s_base = s;
        }
        __syncthreads();
        if (v != 0) {
            int pos = s_w[wid] + __popc(b & ((1u << lane) - 1u));
            if (pos < MAXDEG) g_col[row * MAXDEG + pos] = c0 + tid;
        }
        __syncthreads();
    }
    if (tid == 0) g_cnt[row] = min(s_base, MAXDEG);
}

/* ---------------- K2/K4: fp32 tiled SGEMM (BM=BN=128, BK=8, 8x8/thr) ---- */
__global__ __launch_bounds__(256) void sgemm128(const float* __restrict__ A,
                                                const float* __restrict__ B,
                                                float* __restrict__ C,
                                                int M, int N, int K) {
    __shared__ float As[8][128];
    __shared__ float Bs[8][128];
    const int tid = threadIdx.x;
    const int tx = tid & 15, ty = tid >> 4;
    const int bm = blockIdx.y * 128, bn = blockIdx.x * 128;
    const int aRow = tid >> 1, aCol = (tid & 1) * 4;
    const int bRow = tid >> 5, bCol = (tid & 31) * 4;
    float acc[8][8] = {};
    float4 ra0, ra1, rb0, rb1;
    for (int k0 = 0; k0 < K; k0 += 8) {
        float4 av = *(const float4*)(A + (size_t)(bm + aRow) * K + k0 + aCol);
        As[aCol + 0][aRow] = av.x; As[aCol + 1][aRow] = av.y;
        As[aCol + 2][aRow] = av.z; As[aCol + 3][aRow] = av.w;
        *(float4*)&Bs[bRow][bCol] =
            *(const float4*)(B + (size_t)(k0 + bRow) * N + bn + bCol);
        __syncthreads();
#pragma unroll
        for (int k = 0; k < 8; k++) {
            ra0 = *(float4*)&As[k][ty * 8];
            ra1 = *(float4*)&As[k][ty * 8 + 4];
            rb0 = *(float4*)&Bs[k][tx * 8];
            rb1 = *(float4*)&Bs[k][tx * 8 + 4];
            float ra[8] = {ra0.x, ra0.y, ra0.z, ra0.w, ra1.x, ra1.y, ra1.z, ra1.w};
            float rb[8] = {rb0.x, rb0.y, rb0.z, rb0.w, rb1.x, rb1.y, rb1.z, rb1.w};
#pragma unroll
            for (int i = 0; i < 8; i++)
#pragma unroll
                for (int j = 0; j < 8; j++) acc[i][j] += ra[i] * rb[j];
        }
        __syncthreads();
    }
#pragma unroll
    for (int i = 0; i < 8; i++) {
        float* crow = C + (size_t)(bm + ty * 8 + i) * N + bn + tx * 8;
        *(float4*)(crow)     = make_float4(acc[i][0], acc[i][1], acc[i][2], acc[i][3]);
        *(float4*)(crow + 4) = make_float4(acc[i][4], acc[i][5], acc[i][6], acc[i][7]);
    }
}

/* ---------------- K3: h1 = relu(adj @ XW + b1) ---------------- */
__global__ __launch_bounds__(256) void spmm_relu(const float* __restrict__ b1,
                                                 float* __restrict__ out_cat) {
    int row = blockIdx.x, tid = threadIdx.x;
    __shared__ int s_col[MAXDEG];
    int cnt = g_cnt[row];
    if (tid < cnt) s_col[tid] = g_col[row * MAXDEG + tid];
    __syncthreads();
    float acc = 0.f;
    for (int j = 0; j < cnt; j++)
        acc += g_XW[(size_t)s_col[j] * NHID + tid];
    float h = fmaxf(acc + b1[tid], 0.f);
    g_h1[(size_t)row * NHID + tid] = h;
    out_cat[(size_t)row * CATW + tid] = h;   /* feat part of concat */
}

/* ---------------- K5: f1 = Wh@a[:H], f2 = Wh@a[H:] ---------------- */
__global__ __launch_bounds__(256) void compute_f(const float* __restrict__ a_vec) {
    int lane = threadIdx.x & 31, wid = threadIdx.x >> 5;
    int row  = blockIdx.x * 8 + wid;
    float a1 = 0.f, a2 = 0.f;
    const float* wh = g_Wh + (size_t)row * NHID;
    for (int k = lane; k < NHID; k += 32) {
        float w = wh[k];
        a1 += w * a_vec[k];
        a2 += w * a_vec[NHID + k];
    }
#pragma unroll
    for (int o = 16; o; o >>= 1) {
        a1 += __shfl_down_sync(0xffffffffu, a1, o);
        a2 += __shfl_down_sync(0xffffffffu, a2, o);
    }
    if (lane == 0) { g_f1[row] = a1; g_f2[row] = a2; }
}

/* --------- K6: masked softmax + attention scatter + h'=att@Wh + elu + aW3 --- */
__global__ __launch_bounds__(256) void attn_kernel(float* __restrict__ att_out,
                                                   const float* __restrict__ W3) {
    int row = blockIdx.x, tid = threadIdx.x;
    __shared__ int   s_col[MAXDEG];
    __shared__ float s_att[MAXDEG];
    __shared__ float s_red[256];
    __shared__ float s_a[NHID];
    int cnt = g_cnt[row];
    if (tid < cnt) s_col[tid] = g_col[row * MAXDEG + tid];
    __syncthreads();
    float f1 = g_f1[row];
    float e = -INFINITY;
    if (tid < cnt) {
        float t = f1 + g_f2[s_col[tid]];
        e = (t > 0.f) ? t : ALPHAC * t;
    }
    /* block max */
    s_red[tid] = e;
    __syncthreads();
#pragma unroll
    for (int s = 128; s > 0; s >>= 1) {
        if (tid < s) s_red[tid] = fmaxf(s_red[tid], s_red[tid + s]);
        __syncthreads();
    }
    float m = s_red[0];
    __syncthreads();
    float w = (tid < cnt) ? __expf(e - m) : 0.f;
    s_red[tid] = w;
    __syncthreads();
#pragma unroll
    for (int s = 128; s > 0; s >>= 1) {
        if (tid < s) s_red[tid] += s_red[tid + s];
        __syncthreads();
    }
    float Z = s_red[0];
    __syncthreads();
    if (tid < cnt) {
        float att = w / Z;
        s_att[tid] = att;
        att_out[(size_t)row * Nn + s_col[tid]] = att;   /* scattered nonzeros */
    }
    __syncthreads();
    /* h_prime column gather, tid = hidden channel */
    float acc = 0.f;
    for (int j = 0; j < cnt; j++)
        acc += s_att[j] * g_Wh[(size_t)s_col[j] * NHID + tid];
    float a = (acc > 0.f) ? acc : expm1f(acc);          /* elu */
    s_a[tid] = a;
    __syncthreads();
    /* aW3[row] = a_row @ W3   (256x16) */
    int c = tid >> 4, kk = tid & 15;
    float p = 0.f;
    for (int k = kk; k < NHID; k += 16) p += s_a[k] * W3[k * NCLASS + c];
    s_red[tid] = p;
    __syncthreads();
    if (tid < NCLASS) {
        float s = 0.f;
#pragma unroll
        for (int k = 0; k < 16; k++) s += s_red[tid * 16 + k];
        g_aW3[(size_t)row * NCLASS + tid] = s;
    }
}

/* ---------------- K8: out = adj @ aW3 + b3; sigmoid + concat tail ------- */
__global__ __launch_bounds__(128) void gc3_kernel(const float* __restrict__ b3,
                                                  float* __restrict__ sig_out,
                                                  float* __restrict__ out_cat) {
    int tid = threadIdx.x;
    int r = blockIdx.x * 8 + (tid >> 4);
    int c = tid & 15;
    int cnt = g_cnt[r];
    const int* cols = g_col + r * MAXDEG;
    float acc = 0.f;
    for (int j = 0; j < cnt; j++)
        acc += g_aW3[(size_t)cols[j] * NCLASS + c];
    float o = acc + b3[c];
    sig_out[(size_t)r * NCLASS + c] = 1.f / (1.f + __expf(-o));
    out_cat[(size_t)r * CATW + NHID + c] = o;
}

/* ---------------- launch ---------------- */
extern "C" void kernel_launch(void* const* d_in, const int* in_sizes, int n_in,
                              void* d_out, int out_size) {
    const float* x     = (const float*)d_in[0];
    const int*   adj   = (const int*)  d_in[1];
    const float* W1    = (const float*)d_in[2];
    const float* b1    = (const float*)d_in[3];
    const float* Wa    = (const float*)d_in[4];
    const float* a_vec = (const float*)d_in[5];
    const float* W3    = (const float*)d_in[6];
    const float* b3    = (const float*)d_in[7];

    float* out = (float*)d_out;
    float* sig = out;
    float* att = out + (size_t)Nn * NCLASS;
    float* cat = att + (size_t)Nn * Nn;

    float *pXW, *pH1, *pWh;
    cudaGetSymbolAddress((void**)&pXW, g_XW);
    cudaGetSymbolAddress((void**)&pH1, g_h1);
    cudaGetSymbolAddress((void**)&pWh, g_Wh);

    /* zero the dense attention output (masked entries are exactly 0) */
    cudaMemsetAsync(att, 0, (size_t)Nn * Nn * sizeof(float), 0);

    build_csr<<<Nn, 256>>>(adj);

    /* XW = x @ W1 */
    sgemm128<<<dim3(NHID / 128, Nn / 128), 256>>>(x, W1, pXW, Nn, NHID, NFEATC);

    /* h1 = relu(adj @ XW + b1); also writes feat half of concat */
    spmm_relu<<<Nn, 256>>>(b1, cat);

    /* Wh = h1 @ Wa */
    sgemm128<<<dim3(NHID / 128, Nn / 128), 256>>>(pH1, Wa, pWh, Nn, NHID, NHID);

    compute_f<<<Nn / 8, 256>>>(a_vec);

    attn_kernel<<<Nn, 256>>>(att, W3);

    gc3_kernel<<<Nn / 8, 128>>>(b3, sig, cat);
}

// round 2
// speedup vs baseline: 1.2016x; 1.2016x over previous
#include <cuda_runtime.h>
#include <cuda_fp16.h>
#include <math.h>
#include <stdint.h>

#define Nn      8192
#define NFEATC  512
#define NHID    256
#define NCLASS  16
#define MAXDEG  160
#define ALPHAC  0.01f
#define CATW    (NHID + NCLASS)   /* 272 */

/* ---------------- device scratch ---------------- */
__device__ int    g_col[Nn * MAXDEG];
__device__ int    g_cnt[Nn];
__device__ float  g_XW[Nn * NHID];
__device__ float  g_h1[Nn * NHID];
__device__ float  g_Wh32[Nn * NHID];
__device__ __half g_Whh[Nn * NHID];
__device__ float  g_f1[Nn];
__device__ float  g_f2[Nn];
__device__ float  g_aW3[Nn * NCLASS];

/* ---------------- K1: ordered CSR build (int4 vectorized) ---------------- */
__global__ __launch_bounds__(256) void build_csr(const int4* __restrict__ adj4) {
    int row  = blockIdx.x;
    int tid  = threadIdx.x;
    int lane = tid & 31, wid = tid >> 5;
    __shared__ int s_w[8];
    __shared__ int s_base;
    if (tid == 0) s_base = 0;
    __syncthreads();
    const int4* arow = adj4 + (size_t)row * (Nn / 4);
    /* 8 chunks of 1024 columns */
    for (int c = 0; c < 8; c++) {
        int4 v = arow[c * 256 + tid];
        int n0 = (v.x != 0), n1 = (v.y != 0), n2 = (v.z != 0), n3 = (v.w != 0);
        int cntl = n0 + n1 + n2 + n3;
        /* warp exclusive scan of cntl */
        int excl = cntl;
#pragma unroll
        for (int o = 1; o < 32; o <<= 1) {
            int t = __shfl_up_sync(0xffffffffu, excl, o);
            if (lane >= o) excl += t;
        }
        int wtot = __shfl_sync(0xffffffffu, excl, 31);
        excl -= cntl;
        if (lane == 0) s_w[wid] = wtot;
        __syncthreads();
        if (tid == 0) {
            int s = s_base;
#pragma unroll
            for (int w = 0; w < 8; w++) { int t = s_w[w]; s_w[w] = s; s += t; }
            s_base = s;
        }
        __syncthreads();
        int off = s_w[wid] + excl;
        int base_col = c * 1024 + tid * 4;
        int* dst = g_col + row * MAXDEG;
        if (n0) { if (off < MAXDEG) dst[off] = base_col + 0; off++; }
        if (n1) { if (off < MAXDEG) dst[off] = base_col + 1; off++; }
        if (n2) { if (off < MAXDEG) dst[off] = base_col + 2; off++; }
        if (n3) { if (off < MAXDEG) dst[off] = base_col + 3; off++; }
        __syncthreads();
    }
    if (tid == 0) g_cnt[row] = min(s_base, MAXDEG);
}

/* ------- K2/K4: fp32 SGEMM, 64x64 tile, BK=16, 4x4/thread, 256 thr ------- */
/* DUAL=1 also writes a half-precision copy of C.                            */
template <int DUAL>
__global__ __launch_bounds__(256) void sgemm64(const float* __restrict__ A,
                                               const float* __restrict__ B,
                                               float* __restrict__ C,
                                               __half* __restrict__ Ch,
                                               int M, int N, int K) {
    __shared__ float As[16][64];
    __shared__ float Bs[16][64];
    const int tid = threadIdx.x;
    const int tx = tid & 15, ty = tid >> 4;
    const int bm = blockIdx.y * 64, bn = blockIdx.x * 64;
    const int aRow = tid >> 2, aCol = (tid & 3) * 4;
    const int bRow = tid >> 4, bCol = (tid & 15) * 4;
    float acc[4][4] = {};
    for (int k0 = 0; k0 < K; k0 += 16) {
        float4 av = *(const float4*)(A + (size_t)(bm + aRow) * K + k0 + aCol);
        As[aCol + 0][aRow] = av.x; As[aCol + 1][aRow] = av.y;
        As[aCol + 2][aRow] = av.z; As[aCol + 3][aRow] = av.w;
        *(float4*)&Bs[bRow][bCol] =
            *(const float4*)(B + (size_t)(k0 + bRow) * N + bn + bCol);
        __syncthreads();
#pragma unroll
        for (int k = 0; k < 16; k++) {
            float4 ra = *(float4*)&As[k][ty * 4];
            float4 rb = *(float4*)&Bs[k][tx * 4];
            float a[4] = {ra.x, ra.y, ra.z, ra.w};
            float b[4] = {rb.x, rb.y, rb.z, rb.w};
#pragma unroll
            for (int i = 0; i < 4; i++)
#pragma unroll
                for (int j = 0; j < 4; j++) acc[i][j] += a[i] * b[j];
        }
        __syncthreads();
    }
#pragma unroll
    for (int i = 0; i < 4; i++) {
        int r = bm + ty * 4 + i, c = bn + tx * 4;
        *(float4*)(C + (size_t)r * N + c) =
            make_float4(acc[i][0], acc[i][1], acc[i][2], acc[i][3]);
        if (DUAL) {
            __half2* h2 = (__half2*)(Ch + (size_t)r * N + c);
            h2[0] = __floats2half2_rn(acc[i][0], acc[i][1]);
            h2[1] = __floats2half2_rn(acc[i][2], acc[i][3]);
        }
    }
}

/* ------- K3: h1 = relu(adj@XW + b1); 4 rows/block, float4 channels ------- */
__global__ __launch_bounds__(256) void spmm_relu(const float* __restrict__ b1,
                                                 float* __restrict__ out_cat) {
    const int tid = threadIdx.x;
    const int rl = tid >> 6;            /* row within block: 0..3      */
    const int l64 = tid & 63;           /* 64 threads per row          */
    const int row = blockIdx.x * 4 + rl;
    __shared__ int s_col[4][MAXDEG];
    const int cnt = g_cnt[row];
    for (int j = l64; j < cnt; j += 64) s_col[rl][j] = g_col[row * MAXDEG + j];
    __syncthreads();
    float4 acc = make_float4(0.f, 0.f, 0.f, 0.f);
    const int ch = l64 * 4;
    int j = 0;
    for (; j + 2 <= cnt; j += 2) {
        float4 v0 = *(const float4*)(g_XW + (size_t)s_col[rl][j] * NHID + ch);
        float4 v1 = *(const float4*)(g_XW + (size_t)s_col[rl][j + 1] * NHID + ch);
        acc.x += v0.x + v1.x; acc.y += v0.y + v1.y;
        acc.z += v0.z + v1.z; acc.w += v0.w + v1.w;
    }
    if (j < cnt) {
        float4 v0 = *(const float4*)(g_XW + (size_t)s_col[rl][j] * NHID + ch);
        acc.x += v0.x; acc.y += v0.y; acc.z += v0.z; acc.w += v0.w;
    }
    float4 bb = *(const float4*)(b1 + ch);
    float4 h = make_float4(fmaxf(acc.x + bb.x, 0.f), fmaxf(acc.y + bb.y, 0.f),
                           fmaxf(acc.z + bb.z, 0.f), fmaxf(acc.w + bb.w, 0.f));
    *(float4*)(g_h1 + (size_t)row * NHID + ch) = h;
    *(float4*)(out_cat + (size_t)row * CATW + ch) = h;  /* feat half of concat */
}

/* ---------------- K5: f1 = Wh@a[:H], f2 = Wh@a[H:] (fp32 Wh) ------------- */
__global__ __launch_bounds__(256) void compute_f(const float* __restrict__ a_vec) {
    int lane = threadIdx.x & 31, wid = threadIdx.x >> 5;
    int row  = blockIdx.x * 8 + wid;
    float a1 = 0.f, a2 = 0.f;
    const float* wh = g_Wh32 + (size_t)row * NHID;
#pragma unroll
    for (int k = lane; k < NHID; k += 32) {
        float w = wh[k];
        a1 += w * a_vec[k];
        a2 += w * a_vec[NHID + k];
    }
#pragma unroll
    for (int o = 16; o; o >>= 1) {
        a1 += __shfl_down_sync(0xffffffffu, a1, o);
        a2 += __shfl_down_sync(0xffffffffu, a2, o);
    }
    if (lane == 0) { g_f1[row] = a1; g_f2[row] = a2; }
}

/* -- K6: softmax + FULL attention-row write + h'=att@Wh(half) + elu + aW3 -- */
__global__ __launch_bounds__(256) void attn_kernel(float* __restrict__ att_out,
                                                   const float* __restrict__ W3) {
    const int row = blockIdx.x, tid = threadIdx.x;
    __shared__ float s_row[Nn];          /* 32KB dense attention row */
    __shared__ int   s_col[MAXDEG];
    __shared__ float s_att[MAXDEG];
    __shared__ float s_red[256];
    __shared__ float s_a[NHID];
    const int cnt = g_cnt[row];
    if (tid < cnt) s_col[tid] = g_col[row * MAXDEG + tid];
    /* zero the dense row buffer */
    float4 z4 = make_float4(0.f, 0.f, 0.f, 0.f);
    float4* s4 = (float4*)s_row;
#pragma unroll
    for (int i = 0; i < 8; i++) s4[tid + i * 256] = z4;
    __syncthreads();
    const float f1 = g_f1[row];
    float e = -INFINITY;
    if (tid < cnt) {
        float t = f1 + g_f2[s_col[tid]];
        e = (t > 0.f) ? t : ALPHAC * t;
    }
    s_red[tid] = e;
    __syncthreads();
#pragma unroll
    for (int s = 128; s > 0; s >>= 1) {
        if (tid < s) s_red[tid] = fmaxf(s_red[tid], s_red[tid + s]);
        __syncthreads();
    }
    const float m = s_red[0];
    __syncthreads();
    float w = (tid < cnt) ? __expf(e - m) : 0.f;
    s_red[tid] = w;
    __syncthreads();
#pragma unroll
    for (int s = 128; s > 0; s >>= 1) {
        if (tid < s) s_red[tid] += s_red[tid + s];
        __syncthreads();
    }
    const float Z = s_red[0];
    __syncthreads();
    if (tid < cnt) {
        float att = w / Z;
        s_att[tid] = att;
        s_row[s_col[tid]] = att;
    }
    __syncthreads();
    /* stream out the full dense row (coalesced, replaces the memset pass) */
    float4* orow = (float4*)(att_out + (size_t)row * Nn);
#pragma unroll
    for (int i = 0; i < 8; i++) orow[tid + i * 256] = s4[tid + i * 256];
    /* h_prime channel gather from half-precision Wh */
    float acc = 0.f;
    int j = 0;
    for (; j + 4 <= cnt; j += 4) {
        acc += s_att[j]     * __half2float(g_Whh[(size_t)s_col[j]     * NHID + tid]);
        acc += s_att[j + 1] * __half2float(g_Whh[(size_t)s_col[j + 1] * NHID + tid]);
        acc += s_att[j + 2] * __half2float(g_Whh[(size_t)s_col[j + 2] * NHID + tid]);
        acc += s_att[j + 3] * __half2float(g_Whh[(size_t)s_col[j + 3] * NHID + tid]);
    }
    for (; j < cnt; j++)
        acc += s_att[j] * __half2float(g_Whh[(size_t)s_col[j] * NHID + tid]);
    float a = (acc > 0.f) ? acc : expm1f(acc);          /* elu */
    s_a[tid] = a;
    __syncthreads();
    /* aW3[row] = a_row @ W3 (256x16) */
    int c = tid >> 4, kk = tid & 15;
    float p = 0.f;
    for (int k = kk; k < NHID; k += 16) p += s_a[k] * W3[k * NCLASS + c];
    s_red[tid] = p;
    __syncthreads();
    if (tid < NCLASS) {
        float s = 0.f;
#pragma unroll
        for (int k = 0; k < 16; k++) s += s_red[tid * 16 + k];
        g_aW3[(size_t)row * NCLASS + tid] = s;
    }
}

/* ---------------- K8: out = adj@aW3 + b3; sigmoid + concat tail ---------- */
__global__ __launch_bounds__(128) void gc3_kernel(const float* __restrict__ b3,
                                                  float* __restrict__ sig_out,
                                                  float* __restrict__ out_cat) {
    int tid = threadIdx.x;
    int r = blockIdx.x * 8 + (tid >> 4);
    int c = tid & 15;
    int cnt = g_cnt[r];
    const int* cols = g_col + r * MAXDEG;
    float acc = 0.f;
    for (int j = 0; j < cnt; j++)
        acc += g_aW3[(size_t)cols[j] * NCLASS + c];
    float o = acc + b3[c];
    sig_out[(size_t)r * NCLASS + c] = 1.f / (1.f + __expf(-o));
    out_cat[(size_t)r * CATW + NHID + c] = o;
}

/* ---------------- launch ---------------- */
extern "C" void kernel_launch(void* const* d_in, const int* in_sizes, int n_in,
                              void* d_out, int out_size) {
    const float* x     = (const float*)d_in[0];
    const int*   adj   = (const int*)  d_in[1];
    const float* W1    = (const float*)d_in[2];
    const float* b1    = (const float*)d_in[3];
    const float* Wa    = (const float*)d_in[4];
    const float* a_vec = (const float*)d_in[5];
    const float* W3    = (const float*)d_in[6];
    const float* b3    = (const float*)d_in[7];

    float* out = (float*)d_out;
    float* sig = out;
    float* att = out + (size_t)Nn * NCLASS;
    float* cat = att + (size_t)Nn * Nn;

    float *pXW, *pH1, *pWh32;
    __half* pWhh;
    cudaGetSymbolAddress((void**)&pXW, g_XW);
    cudaGetSymbolAddress((void**)&pH1, g_h1);
    cudaGetSymbolAddress((void**)&pWh32, g_Wh32);
    cudaGetSymbolAddress((void**)&pWhh, g_Whh);

    build_csr<<<Nn, 256>>>((const int4*)adj);

    /* XW = x @ W1  (fp32 only) */
    sgemm64<0><<<dim3(NHID / 64, Nn / 64), 256>>>(x, W1, pXW, nullptr,
                                                  Nn, NHID, NFEATC);

    /* h1 = relu(adj @ XW + b1); also writes feat half of concat */
    spmm_relu<<<Nn / 4, 256>>>(b1, cat);

    /* Wh = h1 @ Wa  (fp32 + fp16 copies) */
    sgemm64<1><<<dim3(NHID / 64, Nn / 64), 256>>>(pH1, Wa, pWh32, pWhh,
                                                  Nn, NHID, NHID);

    compute_f<<<Nn / 8, 256>>>(a_vec);

    attn_kernel<<<Nn, 256>>>(att, W3);

    gc3_kernel<<<Nn / 8, 128>>>(b3, sig, cat);
}